// round 12
// baseline (speedup 1.0000x reference)
#include <cuda_runtime.h>
#include <cstdint>

// Problem constants
#define B_   4096
#define IN_  128
#define H_   1024
#define O_   64
#define T_   25
#define G4   (4*H_)        // 4096 gate columns (interleaved: col = 4*h + gate)
#define KC0  (O_ + H_)     // 1088  layer-0 dynamic K  [y | h1]
#define KC1  (2*H_)        // 2048  layer-1 K          [h1 | h2]

// ---------------------------------------------------------------------------
// Scratch (device globals; no allocation allowed)
// ---------------------------------------------------------------------------
__device__ float g_xs[B_*IN_];          // static input, tf32-rounded
__device__ float g_Ws[G4*IN_];          // W_ih0[:, :128], gate-interleaved rows, tf32
__device__ float g_W0[G4*KC0];          // [W_ih0[:,128:192] | W_hh0], interleaved, tf32
__device__ float g_W1[G4*KC1];          // [W_ih1 | W_hh1], interleaved, tf32
__device__ float g_Wo[O_*H_];           // W_out, tf32
__device__ float g_b0[G4];              // interleaved
__device__ float g_b1[G4];              // interleaved
__device__ float g_Gs[B_*G4];           // static gate pre-activations + b0 (interleaved)
__device__ float g_x0A[B_*KC0];         // ping-pong [y_prev | h1]  (tf32)
__device__ float g_x0B[B_*KC0];
__device__ float g_x1A[B_*KC1];         // ping-pong [h1 | h2]      (tf32)
__device__ float g_x1B[B_*KC1];
__device__ float g_c1[B_*H_];
__device__ float g_c2[B_*H_];

// ---------------------------------------------------------------------------
// Helpers
// ---------------------------------------------------------------------------
__device__ __forceinline__ float to_tf32(float x) {
    float r;
    asm("cvt.rna.tf32.f32 %0, %1;" : "=f"(r) : "f"(x));
    return r;
}
__device__ __forceinline__ float fast_exp2(float x) {
    float r; asm("ex2.approx.f32 %0, %1;" : "=f"(r) : "f"(x)); return r;
}
__device__ __forceinline__ float fast_rcp(float x) {
    float r; asm("rcp.approx.f32 %0, %1;" : "=f"(r) : "f"(x)); return r;
}
__device__ __forceinline__ float sigmoid_f(float x) {
    x = fminf(fmaxf(x, -30.f), 30.f);
    float e = fast_exp2(-x * 1.4426950408889634f);
    return fast_rcp(1.f + e);
}
__device__ __forceinline__ float tanh_f(float x) {
    x = fminf(fmaxf(x, -15.f), 15.f);
    float e = fast_exp2(2.f * x * 1.4426950408889634f);
    return 1.f - 2.f * fast_rcp(e + 1.f);
}
__device__ __forceinline__ void cp16(void* s, const void* g) {
    uint32_t sa = (uint32_t)__cvta_generic_to_shared(s);
    asm volatile("cp.async.cg.shared.global [%0], [%1], 16;\n" :: "r"(sa), "l"(g));
}

// ---------------------------------------------------------------------------
// Prep: ONE kernel packs everything (tf32 + gate interleave + folded biases).
// ---------------------------------------------------------------------------
#define PN0 (B_*IN_)       // xs
#define PN1 (G4*IN_)       // Ws
#define PN2 (G4*KC0)       // W0
#define PN3 (G4*KC1)       // W1
#define PN4 (O_*H_)        // Wo
#define PN5 G4             // b0
#define PN6 G4             // b1
#define PTOT (PN0+PN1+PN2+PN3+PN4+PN5+PN6)

__global__ void prep_all(const float* __restrict__ sIn,
                         const float* __restrict__ Wih0, const float* __restrict__ Whh0,
                         const float* __restrict__ bih0, const float* __restrict__ bhh0,
                         const float* __restrict__ Wih1, const float* __restrict__ Whh1,
                         const float* __restrict__ bih1, const float* __restrict__ bhh1,
                         const float* __restrict__ Wout,
                         float* __restrict__ xs, float* __restrict__ Ws,
                         float* __restrict__ W0, float* __restrict__ W1,
                         float* __restrict__ Wo, float* __restrict__ b0,
                         float* __restrict__ b1)
{
    for (long long i = blockIdx.x * (long long)blockDim.x + threadIdx.x; i < PTOT;
         i += (long long)gridDim.x * blockDim.x) {
        long long j = i;
        if (j < PN0) { xs[j] = to_tf32(sIn[j]); continue; }
        j -= PN0;
        if (j < PN1) {
            int r = (int)(j / IN_), k = (int)(j - (long long)r * IN_);
            int p = (r & 3) * H_ + (r >> 2);
            Ws[j] = to_tf32(Wih0[p * (IN_ + O_) + k]);
            continue;
        }
        j -= PN1;
        if (j < PN2) {
            int r = (int)(j / KC0), k = (int)(j - (long long)r * KC0);
            int p = (r & 3) * H_ + (r >> 2);
            float v = (k < O_) ? Wih0[p * (IN_ + O_) + IN_ + k]
                               : Whh0[p * H_ + (k - O_)];
            W0[j] = to_tf32(v);
            continue;
        }
        j -= PN2;
        if (j < PN3) {
            int r = (int)(j / KC1), k = (int)(j - (long long)r * KC1);
            int p = (r & 3) * H_ + (r >> 2);
            float v = (k < H_) ? Wih1[p * H_ + k] : Whh1[p * H_ + (k - H_)];
            W1[j] = to_tf32(v);
            continue;
        }
        j -= PN3;
        if (j < PN4) { Wo[j] = to_tf32(Wout[j]); continue; }
        j -= PN4;
        if (j < PN5) {
            int p = ((int)j & 3) * H_ + ((int)j >> 2);
            b0[j] = bih0[p] + bhh0[p];
            continue;
        }
        j -= PN5;
        {
            int p = ((int)j & 3) * H_ + ((int)j >> 2);
            b1[j] = bih1[p] + bhh1[p];
        }
    }
}

__global__ void zero2(float* __restrict__ p1, int n1, float* __restrict__ p2, int n2)
{
    for (int i = blockIdx.x * blockDim.x + threadIdx.x; i < n1 + n2;
         i += gridDim.x * blockDim.x) {
        if (i < n1) p1[i] = 0.f; else p2[i - n1] = 0.f;
    }
}

// ---------------------------------------------------------------------------
// TF32 GEMM (R5 shape + double buffer + fused cell epilogue):
//   acc[M,N] = A[M,K] * W[N,K]^T
// BM=128, BN=64, BK=32, STAGES=2, 8 warps (4 M x 2 N), warp tile 32x32,
// mma.sync.m16n8k8.tf32, scalar LDS fragment loads (conflict-free w/ PAD=36).
// Smem 55.3 KB -> multiple CTAs/SM; 32 accumulators -> no spills.
// MODE 0: C = acc + bias
// MODE 1: fused LSTM cell epilogue (gate-interleaved columns).
// ---------------------------------------------------------------------------
#define BM 128
#define BN 64
#define BK 32
#define PAD 36
#define STG_A (BM*PAD)
#define STG_B (BN*PAD)
#define SMEM_BYTES (2*(STG_A+STG_B)*4)

template<int MODE>
__global__ void __launch_bounds__(256)
gemm_fused(int K,
           const float* __restrict__ A, int lda,
           const float* __restrict__ Bw, int ldb,
           float* __restrict__ C,
           const float* __restrict__ Ci,
           const float* __restrict__ bias,
           float* __restrict__ cst,
           float* __restrict__ hd1, int ldh1,
           float* __restrict__ hd2, int ldh2)
{
    extern __shared__ float sm[];
    float* Asm = sm;                 // [2][BM][PAD]
    float* Bsm = sm + 2 * STG_A;     // [2][BN][PAD]

    const int tid  = threadIdx.x;
    const int warp = tid >> 5;
    const int lane = tid & 31;
    const int wm = (warp & 3) * 32;   // warp M offset
    const int wn = (warp >> 2) * 32;  // warp N offset
    const int bm0 = blockIdx.y * BM;
    const int bn0 = blockIdx.x * BN;

    const float* Ablk = A + bm0 * lda;
    const float* Bblk = Bw + bn0 * ldb;

    float c[2][4][4];
#pragma unroll
    for (int mt = 0; mt < 2; mt++)
#pragma unroll
        for (int nt = 0; nt < 4; nt++)
#pragma unroll
            for (int r = 0; r < 4; r++) c[mt][nt][r] = 0.f;

    const int numTiles = K / BK;

    auto loadStage = [&](int st, int k0) {
        float* As = Asm + st * STG_A;
        float* Bs = Bsm + st * STG_B;
#pragma unroll
        for (int i = 0; i < 4; i++) {             // A: 1024 16B chunks
            int cc = tid + i * 256;
            int r = cc >> 3, kc = (cc & 7) << 2;
            cp16(&As[r * PAD + kc], Ablk + r * lda + k0 + kc);
        }
#pragma unroll
        for (int i = 0; i < 2; i++) {             // B: 512 16B chunks
            int cc = tid + i * 256;
            int r = cc >> 3, kc = (cc & 7) << 2;
            cp16(&Bs[r * PAD + kc], Bblk + r * ldb + k0 + kc);
        }
    };

    loadStage(0, 0);
    asm volatile("cp.async.commit_group;\n" ::);

    for (int it = 0; it < numTiles; ++it) {
        // issue prefetch of next tile into the other stage
        if (it + 1 < numTiles) {
            loadStage((it + 1) & 1, (it + 1) * BK);
            asm volatile("cp.async.commit_group;\n" ::);
            asm volatile("cp.async.wait_group 1;\n" ::);   // current stage ready
        } else {
            asm volatile("cp.async.wait_group 0;\n" ::);
        }
        __syncthreads();

        const float* As = Asm + (it & 1) * STG_A;
        const float* Bs = Bsm + (it & 1) * STG_B;

#pragma unroll
        for (int kk = 0; kk < 4; kk++) {
            const int kb = kk * 8 + (lane & 3);
            uint32_t af[2][4], bf[4][2];
#pragma unroll
            for (int mt = 0; mt < 2; mt++) {
                int m = wm + mt * 16 + (lane >> 2);
                af[mt][0] = __float_as_uint(As[m * PAD + kb]);
                af[mt][1] = __float_as_uint(As[(m + 8) * PAD + kb]);
                af[mt][2] = __float_as_uint(As[m * PAD + kb + 4]);
                af[mt][3] = __float_as_uint(As[(m + 8) * PAD + kb + 4]);
            }
#pragma unroll
            for (int nt = 0; nt < 4; nt++) {
                int n = wn + nt * 8 + (lane >> 2);
                bf[nt][0] = __float_as_uint(Bs[n * PAD + kb]);
                bf[nt][1] = __float_as_uint(Bs[n * PAD + kb + 4]);
            }
#pragma unroll
            for (int mt = 0; mt < 2; mt++)
#pragma unroll
                for (int nt = 0; nt < 4; nt++)
                    asm volatile(
                        "mma.sync.aligned.m16n8k8.row.col.f32.tf32.tf32.f32 "
                        "{%0,%1,%2,%3}, {%4,%5,%6,%7}, {%8,%9}, {%0,%1,%2,%3};\n"
                        : "+f"(c[mt][nt][0]), "+f"(c[mt][nt][1]),
                          "+f"(c[mt][nt][2]), "+f"(c[mt][nt][3])
                        : "r"(af[mt][0]), "r"(af[mt][1]),
                          "r"(af[mt][2]), "r"(af[mt][3]),
                        "r"(bf[nt][0]), "r"(bf[nt][1]));
        }
        __syncthreads();   // all warps done with this stage before it is refilled
    }

    // ---- epilogue ----
#pragma unroll
    for (int mt = 0; mt < 2; mt++) {
#pragma unroll
        for (int nt = 0; nt < 4; nt++) {
            int m = bm0 + wm + mt * 16 + (lane >> 2);
            int n = bn0 + wn + nt * 8 + ((lane & 3) << 1);
            float v0 = c[mt][nt][0], v1 = c[mt][nt][1];
            float v2 = c[mt][nt][2], v3 = c[mt][nt][3];

            if (MODE == 0) {
                float bv0 = bias[n], bv1 = bias[n + 1];
                C[m * G4 + n]           = v0 + bv0;
                C[m * G4 + n + 1]       = v1 + bv1;
                C[(m + 8) * G4 + n]     = v2 + bv0;
                C[(m + 8) * G4 + n + 1] = v3 + bv1;
            } else {
                if (Ci) {
                    v0 += Ci[m * G4 + n];
                    v1 += Ci[m * G4 + n + 1];
                    v2 += Ci[(m + 8) * G4 + n];
                    v3 += Ci[(m + 8) * G4 + n + 1];
                } else {
                    v0 += bias[n];     v1 += bias[n + 1];
                    v2 += bias[n];     v3 += bias[n + 1];
                }
                // Gate exchange with lane^1 partner:
                // even lane (cols 4h,4h+1 = i,f) -> row m;
                // odd  lane (cols 4h+2,4h+3 = g,o) -> row m+8.
                float e0 = __shfl_xor_sync(0xffffffffu, v0, 1);
                float e1 = __shfl_xor_sync(0xffffffffu, v1, 1);
                float e2 = __shfl_xor_sync(0xffffffffu, v2, 1);
                float e3 = __shfl_xor_sync(0xffffffffu, v3, 1);
                int h = n >> 2;
                int row; float gi, gf, gg, go;
                if ((lane & 1) == 0) { row = m;     gi = v0; gf = v1; gg = e0; go = e1; }
                else                 { row = m + 8; gi = e2; gf = e3; gg = v2; go = v3; }

                float cold = cst[row * H_ + h];
                float I = sigmoid_f(gi), F = sigmoid_f(gf);
                float G = tanh_f(gg),    Oo = sigmoid_f(go);
                float nc = F * cold + I * G;
                float nh = to_tf32(Oo * tanh_f(nc));
                cst[row * H_ + h] = nc;
                hd1[row * ldh1 + h] = nh;
                if (hd2) hd2[row * ldh2 + h] = nh;
            }
        }
    }
}

// ---------------------------------------------------------------------------
// Output GEMM (N=64): y = h2 @ Wout^T + bout, fused scatter to d_out[:,t,:]
// and tf32 feedback into x0_next[:, 0:64]. grid (1, 32).
// ---------------------------------------------------------------------------
__global__ void __launch_bounds__(256)
gemm_out(const float* __restrict__ A, int lda,
         const float* __restrict__ Bw,
         const float* __restrict__ bias,
         float* __restrict__ out, float* __restrict__ x0n, int t)
{
    __shared__ float As[128][BK + 4];
    __shared__ float Bs[64][BK + 4];

    const int tid  = threadIdx.x;
    const int warp = tid >> 5;
    const int lane = tid & 31;
    const int wm = (warp & 3) * 32;
    const int wn = (warp >> 2) * 32;
    const int bm0 = blockIdx.y * 128;

    float c[2][4][4];
#pragma unroll
    for (int mt = 0; mt < 2; mt++)
#pragma unroll
        for (int nt = 0; nt < 4; nt++)
#pragma unroll
            for (int r = 0; r < 4; r++) c[mt][nt][r] = 0.f;

    const float* Ablk = A + bm0 * lda;

    for (int k0 = 0; k0 < H_; k0 += BK) {
#pragma unroll
        for (int i = 0; i < 4; i++) {
            int cc = tid + i * 256;
            int r = cc >> 3, kc = (cc & 7) << 2;
            cp16(&As[r][kc], Ablk + r * lda + k0 + kc);
        }
#pragma unroll
        for (int i = 0; i < 2; i++) {
            int cc = tid + i * 256;
            int r = cc >> 3, kc = (cc & 7) << 2;
            cp16(&Bs[r][kc], Bw + r * H_ + k0 + kc);
        }
        asm volatile("cp.async.commit_group;\n" ::);
        asm volatile("cp.async.wait_group 0;\n" ::);
        __syncthreads();

#pragma unroll
        for (int kk = 0; kk < 4; kk++) {
            const int kb = kk * 8 + (lane & 3);
            uint32_t af[2][4], bf[4][2];
#pragma unroll
            for (int mt = 0; mt < 2; mt++) {
                int m = wm + mt * 16 + (lane >> 2);
                af[mt][0] = __float_as_uint(As[m    ][kb    ]);
                af[mt][1] = __float_as_uint(As[m + 8][kb    ]);
                af[mt][2] = __float_as_uint(As[m    ][kb + 4]);
                af[mt][3] = __float_as_uint(As[m + 8][kb + 4]);
            }
#pragma unroll
            for (int nt = 0; nt < 4; nt++) {
                int n = wn + nt * 8 + (lane >> 2);
                bf[nt][0] = __float_as_uint(Bs[n][kb    ]);
                bf[nt][1] = __float_as_uint(Bs[n][kb + 4]);
            }
#pragma unroll
            for (int mt = 0; mt < 2; mt++)
#pragma unroll
                for (int nt = 0; nt < 4; nt++)
                    asm volatile(
                        "mma.sync.aligned.m16n8k8.row.col.f32.tf32.tf32.f32 "
                        "{%0,%1,%2,%3}, {%4,%5,%6,%7}, {%8,%9}, {%0,%1,%2,%3};\n"
                        : "+f"(c[mt][nt][0]), "+f"(c[mt][nt][1]),
                          "+f"(c[mt][nt][2]), "+f"(c[mt][nt][3])
                        : "r"(af[mt][0]), "r"(af[mt][1]),
                          "r"(af[mt][2]), "r"(af[mt][3]),
                          "r"(bf[nt][0]), "r"(bf[nt][1]));
        }
        __syncthreads();
    }

#pragma unroll
    for (int mt = 0; mt < 2; mt++) {
#pragma unroll
        for (int nt = 0; nt < 4; nt++) {
            int m = bm0 + wm + mt * 16 + (lane >> 2);
            int n = wn + nt * 8 + ((lane & 3) << 1);
            float bv0 = bias[n], bv1 = bias[n + 1];
            float v0 = c[mt][nt][0] + bv0;
            float v1 = c[mt][nt][1] + bv1;
            float v2 = c[mt][nt][2] + bv0;
            float v3 = c[mt][nt][3] + bv1;
            out[m * (T_ * O_) + t * O_ + n]           = v0;
            out[m * (T_ * O_) + t * O_ + n + 1]       = v1;
            out[(m + 8) * (T_ * O_) + t * O_ + n]     = v2;
            out[(m + 8) * (T_ * O_) + t * O_ + n + 1] = v3;
            x0n[m * KC0 + n]           = to_tf32(v0);
            x0n[m * KC0 + n + 1]       = to_tf32(v1);
            x0n[(m + 8) * KC0 + n]     = to_tf32(v2);
            x0n[(m + 8) * KC0 + n + 1] = to_tf32(v3);
        }
    }
}

// ---------------------------------------------------------------------------
// Launch. ncu -s 5 -c 1 captures launch 5 = layer-1 GEMM (t=0):
// 0 prep_all, 1 zero2, 2 zero2, 3 Gs, 4 L0(t0), 5 L1(t0).
// ---------------------------------------------------------------------------
extern "C" void kernel_launch(void* const* d_in, const int* in_sizes, int n_in,
                              void* d_out, int out_size)
{
    (void)in_sizes; (void)n_in; (void)out_size;
    const float* sIn  = (const float*)d_in[0];
    const float* Wih0 = (const float*)d_in[1];
    const float* Whh0 = (const float*)d_in[2];
    const float* bih0 = (const float*)d_in[3];
    const float* bhh0 = (const float*)d_in[4];
    const float* Wih1 = (const float*)d_in[5];
    const float* Whh1 = (const float*)d_in[6];
    const float* bih1 = (const float*)d_in[7];
    const float* bhh1 = (const float*)d_in[8];
    const float* Wout = (const float*)d_in[9];
    const float* bout = (const float*)d_in[10];
    float* out = (float*)d_out;

    float *xs, *Ws, *W0, *W1, *Wo, *b0, *b1, *Gs, *x0A, *x0B, *x1A, *x1B, *c1, *c2;
    cudaGetSymbolAddress((void**)&xs,  g_xs);
    cudaGetSymbolAddress((void**)&Ws,  g_Ws);
    cudaGetSymbolAddress((void**)&W0,  g_W0);
    cudaGetSymbolAddress((void**)&W1,  g_W1);
    cudaGetSymbolAddress((void**)&Wo,  g_Wo);
    cudaGetSymbolAddress((void**)&b0,  g_b0);
    cudaGetSymbolAddress((void**)&b1,  g_b1);
    cudaGetSymbolAddress((void**)&Gs,  g_Gs);
    cudaGetSymbolAddress((void**)&x0A, g_x0A);
    cudaGetSymbolAddress((void**)&x0B, g_x0B);
    cudaGetSymbolAddress((void**)&x1A, g_x1A);
    cudaGetSymbolAddress((void**)&x1B, g_x1B);
    cudaGetSymbolAddress((void**)&c1,  g_c1);
    cudaGetSymbolAddress((void**)&c2,  g_c2);

    static bool attr_done = false;
    if (!attr_done) {
        cudaFuncSetAttribute(gemm_fused<0>,
            cudaFuncAttributeMaxDynamicSharedMemorySize, SMEM_BYTES);
        cudaFuncSetAttribute(gemm_fused<1>,
            cudaFuncAttributeMaxDynamicSharedMemorySize, SMEM_BYTES);
        attr_done = true;
    }

    // launch 0: pack everything
    prep_all<<<4096, 256>>>(sIn, Wih0, Whh0, bih0, bhh0, Wih1, Whh1, bih1, bhh1,
                            Wout, xs, Ws, W0, W1, Wo, b0, b1);
    // launches 1-2: zero recurrent state (replay reset)
    zero2<<<4096, 256>>>(x0A, B_ * KC0, c1, B_ * H_);
    zero2<<<4096, 256>>>(x1A, B_ * KC1, c2, B_ * H_);

    // launch 3: Gs = static @ Ws^T + b0
    dim3 grid(G4 / BN, B_ / BM);   // (64, 32)
    gemm_fused<0><<<grid, 256, SMEM_BYTES>>>(IN_, xs, IN_, Ws, IN_,
                                             Gs, nullptr, b0,
                                             nullptr, nullptr, 0, nullptr, 0);

    float* x0b[2] = {x0A, x0B};
    float* x1b[2] = {x1A, x1B};
    dim3 gridOut(1, B_ / 128);     // (1, 32)

    for (int t = 0; t < T_; t++) {
        float* x0c = x0b[t & 1];
        float* x0n = x0b[(t + 1) & 1];
        float* x1c = x1b[t & 1];
        float* x1n = x1b[(t + 1) & 1];

        // layer 0: gates = [y|h1]@W0^T + Gs ; cell -> c1, h1 into x0n & x1c
        gemm_fused<1><<<grid, 256, SMEM_BYTES>>>(KC0, x0c, KC0, W0, KC0,
                                                 nullptr, Gs, nullptr,
                                                 c1, x0n + O_, KC0, x1c, KC1);

        // layer 1: gates = [h1|h2]@W1^T + b1 ; cell -> c2, h2 into x1n second half
        gemm_fused<1><<<grid, 256, SMEM_BYTES>>>(KC1, x1c, KC1, W1, KC1,
                                                 nullptr, nullptr, b1,
                                                 c2, x1n + H_, KC1, nullptr, 0);

        // output: y = h2 @ Wout^T + bout ; fused scatter + feedback into x0n
        gemm_out<<<gridOut, 256>>>(x1n + H_, KC1, Wo, bout, out, x0n, t);
    }
}

// round 13
// speedup vs baseline: 1.6370x; 1.6370x over previous
#include <cuda_runtime.h>
#include <cstdint>

// Problem constants
#define B_   4096
#define IN_  128
#define H_   1024
#define O_   64
#define T_   25
#define G4   (4*H_)        // 4096 gate columns (interleaved: col = 4*h + gate)
#define KC0  (O_ + H_)     // 1088  layer-0 dynamic K  [y | h1]
#define KC1  (2*H_)        // 2048  layer-1 K          [h1 | h2]

// ---------------------------------------------------------------------------
// Scratch (device globals; no allocation allowed)
// ---------------------------------------------------------------------------
__device__ float g_xs[B_*IN_];          // static input, tf32-rounded
__device__ float g_Ws[G4*IN_];          // W_ih0[:, :128], gate-interleaved rows, tf32
__device__ float g_W0[G4*KC0];          // [W_ih0[:,128:192] | W_hh0], interleaved, tf32
__device__ float g_W1[G4*KC1];          // [W_ih1 | W_hh1], interleaved, tf32
__device__ float g_Wo[O_*H_];           // W_out, tf32
__device__ float g_b0[G4];              // interleaved
__device__ float g_b1[G4];              // interleaved
__device__ float g_Gs[B_*G4];           // static gate pre-activations + b0 (interleaved)
__device__ float g_x0A[B_*KC0];         // ping-pong [y_prev | h1]  (tf32)
__device__ float g_x0B[B_*KC0];
__device__ float g_x1A[B_*KC1];         // ping-pong [h1 | h2]      (tf32)
__device__ float g_x1B[B_*KC1];
__device__ float g_c1[B_*H_];
__device__ float g_c2[B_*H_];

// ---------------------------------------------------------------------------
// Helpers
// ---------------------------------------------------------------------------
__device__ __forceinline__ float to_tf32(float x) {
    float r;
    asm("cvt.rna.tf32.f32 %0, %1;" : "=f"(r) : "f"(x));
    return r;
}
__device__ __forceinline__ float fast_exp2(float x) {
    float r; asm("ex2.approx.f32 %0, %1;" : "=f"(r) : "f"(x)); return r;
}
__device__ __forceinline__ float fast_rcp(float x) {
    float r; asm("rcp.approx.f32 %0, %1;" : "=f"(r) : "f"(x)); return r;
}
__device__ __forceinline__ float sigmoid_f(float x) {
    x = fminf(fmaxf(x, -30.f), 30.f);
    float e = fast_exp2(-x * 1.4426950408889634f);
    return fast_rcp(1.f + e);
}
__device__ __forceinline__ float tanh_f(float x) {
    x = fminf(fmaxf(x, -15.f), 15.f);
    float e = fast_exp2(2.f * x * 1.4426950408889634f);
    return 1.f - 2.f * fast_rcp(e + 1.f);
}
__device__ __forceinline__ void cp16(void* s, const void* g) {
    uint32_t sa = (uint32_t)__cvta_generic_to_shared(s);
    asm volatile("cp.async.cg.shared.global [%0], [%1], 16;\n" :: "r"(sa), "l"(g));
}

// ---------------------------------------------------------------------------
// Prep: ONE kernel packs everything (tf32 + gate interleave + folded biases).
// ---------------------------------------------------------------------------
#define PN0 (B_*IN_)       // xs
#define PN1 (G4*IN_)       // Ws
#define PN2 (G4*KC0)       // W0
#define PN3 (G4*KC1)       // W1
#define PN4 (O_*H_)        // Wo
#define PN5 G4             // b0
#define PN6 G4             // b1
#define PTOT (PN0+PN1+PN2+PN3+PN4+PN5+PN6)

__global__ void prep_all(const float* __restrict__ sIn,
                         const float* __restrict__ Wih0, const float* __restrict__ Whh0,
                         const float* __restrict__ bih0, const float* __restrict__ bhh0,
                         const float* __restrict__ Wih1, const float* __restrict__ Whh1,
                         const float* __restrict__ bih1, const float* __restrict__ bhh1,
                         const float* __restrict__ Wout,
                         float* __restrict__ xs, float* __restrict__ Ws,
                         float* __restrict__ W0, float* __restrict__ W1,
                         float* __restrict__ Wo, float* __restrict__ b0,
                         float* __restrict__ b1)
{
    for (long long i = blockIdx.x * (long long)blockDim.x + threadIdx.x; i < PTOT;
         i += (long long)gridDim.x * blockDim.x) {
        long long j = i;
        if (j < PN0) { xs[j] = to_tf32(sIn[j]); continue; }
        j -= PN0;
        if (j < PN1) {
            int r = (int)(j / IN_), k = (int)(j - (long long)r * IN_);
            int p = (r & 3) * H_ + (r >> 2);
            Ws[j] = to_tf32(Wih0[p * (IN_ + O_) + k]);
            continue;
        }
        j -= PN1;
        if (j < PN2) {
            int r = (int)(j / KC0), k = (int)(j - (long long)r * KC0);
            int p = (r & 3) * H_ + (r >> 2);
            float v = (k < O_) ? Wih0[p * (IN_ + O_) + IN_ + k]
                               : Whh0[p * H_ + (k - O_)];
            W0[j] = to_tf32(v);
            continue;
        }
        j -= PN2;
        if (j < PN3) {
            int r = (int)(j / KC1), k = (int)(j - (long long)r * KC1);
            int p = (r & 3) * H_ + (r >> 2);
            float v = (k < H_) ? Wih1[p * H_ + k] : Whh1[p * H_ + (k - H_)];
            W1[j] = to_tf32(v);
            continue;
        }
        j -= PN3;
        if (j < PN4) { Wo[j] = to_tf32(Wout[j]); continue; }
        j -= PN4;
        if (j < PN5) {
            int p = ((int)j & 3) * H_ + ((int)j >> 2);
            b0[j] = bih0[p] + bhh0[p];
            continue;
        }
        j -= PN5;
        {
            int p = ((int)j & 3) * H_ + ((int)j >> 2);
            b1[j] = bih1[p] + bhh1[p];
        }
    }
}

__global__ void zero2(float* __restrict__ p1, int n1, float* __restrict__ p2, int n2)
{
    for (int i = blockIdx.x * blockDim.x + threadIdx.x; i < n1 + n2;
         i += gridDim.x * blockDim.x) {
        if (i < n1) p1[i] = 0.f; else p2[i - n1] = 0.f;
    }
}

// ---------------------------------------------------------------------------
// TF32 GEMM: acc[M,N] = A[M,K] * W[N,K]^T
// BM=128, BN=64, BK=32, 2-stage cp.async, 8 warps (4 M x 2 N), warp 32x32,
// mma.sync.m16n8k8.tf32, scalar LDS fragments (conflict-free, PAD=36).
// MODE 0: C = acc + bias (direct store)
// MODE 1: fused LSTM cell via SMEM-STAGED COALESCED epilogue:
//   accumulators -> smem [128][68]; re-read with h-contiguous threads;
//   one float4 = (i,f,g,o) per (row,h); coalesced c/h global traffic.
// ---------------------------------------------------------------------------
#define BM 128
#define BN 64
#define BK 32
#define PAD 36
#define STG_A (BM*PAD)
#define STG_B (BN*PAD)
#define SMEM_BYTES (2*(STG_A+STG_B)*4)
#define EPI_LD 68          // epilogue smem row stride (floats); 68*4B % 16B == 0

template<int MODE>
__global__ void __launch_bounds__(256)
gemm_fused(int K,
           const float* __restrict__ A, int lda,
           const float* __restrict__ Bw, int ldb,
           float* __restrict__ C,
           const float* __restrict__ Ci,
           const float* __restrict__ bias,
           float* __restrict__ cst,
           float* __restrict__ hd1, int ldh1,
           float* __restrict__ hd2, int ldh2)
{
    extern __shared__ float sm[];
    float* Asm = sm;                 // [2][BM][PAD]
    float* Bsm = sm + 2 * STG_A;     // [2][BN][PAD]

    const int tid  = threadIdx.x;
    const int warp = tid >> 5;
    const int lane = tid & 31;
    const int wm = (warp & 3) * 32;   // warp M offset
    const int wn = (warp >> 2) * 32;  // warp N offset
    const int bm0 = blockIdx.y * BM;
    const int bn0 = blockIdx.x * BN;

    const float* Ablk = A + bm0 * lda;
    const float* Bblk = Bw + bn0 * ldb;

    float c[2][4][4];
#pragma unroll
    for (int mt = 0; mt < 2; mt++)
#pragma unroll
        for (int nt = 0; nt < 4; nt++)
#pragma unroll
            for (int r = 0; r < 4; r++) c[mt][nt][r] = 0.f;

    const int numTiles = K / BK;

    auto loadStage = [&](int st, int k0) {
        float* As = Asm + st * STG_A;
        float* Bs = Bsm + st * STG_B;
#pragma unroll
        for (int i = 0; i < 4; i++) {             // A: 1024 16B chunks
            int cc = tid + i * 256;
            int r = cc >> 3, kc = (cc & 7) << 2;
            cp16(&As[r * PAD + kc], Ablk + r * lda + k0 + kc);
        }
#pragma unroll
        for (int i = 0; i < 2; i++) {             // B: 512 16B chunks
            int cc = tid + i * 256;
            int r = cc >> 3, kc = (cc & 7) << 2;
            cp16(&Bs[r * PAD + kc], Bblk + r * ldb + k0 + kc);
        }
    };

    loadStage(0, 0);
    asm volatile("cp.async.commit_group;\n" ::);

    for (int it = 0; it < numTiles; ++it) {
        if (it + 1 < numTiles) {
            loadStage((it + 1) & 1, (it + 1) * BK);
            asm volatile("cp.async.commit_group;\n" ::);
            asm volatile("cp.async.wait_group 1;\n" ::);
        } else {
            asm volatile("cp.async.wait_group 0;\n" ::);
        }
        __syncthreads();

        const float* As = Asm + (it & 1) * STG_A;
        const float* Bs = Bsm + (it & 1) * STG_B;

#pragma unroll
        for (int kk = 0; kk < 4; kk++) {
            const int kb = kk * 8 + (lane & 3);
            uint32_t af[2][4], bf[4][2];
#pragma unroll
            for (int mt = 0; mt < 2; mt++) {
                int m = wm + mt * 16 + (lane >> 2);
                af[mt][0] = __float_as_uint(As[m * PAD + kb]);
                af[mt][1] = __float_as_uint(As[(m + 8) * PAD + kb]);
                af[mt][2] = __float_as_uint(As[m * PAD + kb + 4]);
                af[mt][3] = __float_as_uint(As[(m + 8) * PAD + kb + 4]);
            }
#pragma unroll
            for (int nt = 0; nt < 4; nt++) {
                int n = wn + nt * 8 + (lane >> 2);
                bf[nt][0] = __float_as_uint(Bs[n * PAD + kb]);
                bf[nt][1] = __float_as_uint(Bs[n * PAD + kb + 4]);
            }
#pragma unroll
            for (int mt = 0; mt < 2; mt++)
#pragma unroll
                for (int nt = 0; nt < 4; nt++)
                    asm volatile(
                        "mma.sync.aligned.m16n8k8.row.col.f32.tf32.tf32.f32 "
                        "{%0,%1,%2,%3}, {%4,%5,%6,%7}, {%8,%9}, {%0,%1,%2,%3};\n"
                        : "+f"(c[mt][nt][0]), "+f"(c[mt][nt][1]),
                          "+f"(c[mt][nt][2]), "+f"(c[mt][nt][3])
                        : "r"(af[mt][0]), "r"(af[mt][1]),
                          "r"(af[mt][2]), "r"(af[mt][3]),
                        "r"(bf[nt][0]), "r"(bf[nt][1]));
        }
        __syncthreads();
    }

    if (MODE == 0) {
        // direct store (runs once per replay; coalescing non-critical)
#pragma unroll
        for (int mt = 0; mt < 2; mt++) {
#pragma unroll
            for (int nt = 0; nt < 4; nt++) {
                int m = bm0 + wm + mt * 16 + (lane >> 2);
                int n = bn0 + wn + nt * 8 + ((lane & 3) << 1);
                float bv0 = bias[n], bv1 = bias[n + 1];
                C[m * G4 + n]           = c[mt][nt][0] + bv0;
                C[m * G4 + n + 1]       = c[mt][nt][1] + bv1;
                C[(m + 8) * G4 + n]     = c[mt][nt][2] + bv0;
                C[(m + 8) * G4 + n + 1] = c[mt][nt][3] + bv1;
            }
        }
    } else {
        // ---- staged, coalesced fused-cell epilogue ----
        float* Gsm = sm;   // mainloop buffers are dead; 128*68 floats fit easily
#pragma unroll
        for (int mt = 0; mt < 2; mt++) {
#pragma unroll
            for (int nt = 0; nt < 4; nt++) {
                int m = wm + mt * 16 + (lane >> 2);
                int n = wn + nt * 8 + ((lane & 3) << 1);
                Gsm[m * EPI_LD + n]           = c[mt][nt][0];
                Gsm[m * EPI_LD + n + 1]       = c[mt][nt][1];
                Gsm[(m + 8) * EPI_LD + n]     = c[mt][nt][2];
                Gsm[(m + 8) * EPI_LD + n + 1] = c[mt][nt][3];
            }
        }
        __syncthreads();

        const int hbase = bn0 >> 2;   // 16 h-values per CTA
#pragma unroll
        for (int i = 0; i < 8; i++) {
            int idx = tid + i * 256;          // 2048 cells = 128 rows x 16 h
            int h = idx & 15;
            int r = idx >> 4;
            int rg = bm0 + r;
            int hg = hbase + h;

            float4 g = *(float4*)&Gsm[r * EPI_LD + (h << 2)];
            if (Ci) {
                const float4 ci = *(const float4*)(Ci + (long long)rg * G4 + bn0 + (h << 2));
                g.x += ci.x; g.y += ci.y; g.z += ci.z; g.w += ci.w;
            } else {
                const float4 bb = *(const float4*)(bias + bn0 + (h << 2));
                g.x += bb.x; g.y += bb.y; g.z += bb.z; g.w += bb.w;
            }
            float cold = cst[rg * H_ + hg];
            float I = sigmoid_f(g.x), F = sigmoid_f(g.y);
            float G = tanh_f(g.z),    Oo = sigmoid_f(g.w);
            float nc = F * cold + I * G;
            float nh = to_tf32(Oo * tanh_f(nc));
            cst[rg * H_ + hg]   = nc;
            hd1[rg * ldh1 + hg] = nh;
            if (hd2) hd2[rg * ldh2 + hg] = nh;
        }
    }
}

// ---------------------------------------------------------------------------
// Output GEMM (N=64): y = h2 @ Wout^T + bout, fused scatter to d_out[:,t,:]
// and tf32 feedback into x0_next[:, 0:64]. grid (1, 32).
// ---------------------------------------------------------------------------
__global__ void __launch_bounds__(256)
gemm_out(const float* __restrict__ A, int lda,
         const float* __restrict__ Bw,
         const float* __restrict__ bias,
         float* __restrict__ out, float* __restrict__ x0n, int t)
{
    __shared__ float As[128][BK + 4];
    __shared__ float Bs[64][BK + 4];

    const int tid  = threadIdx.x;
    const int warp = tid >> 5;
    const int lane = tid & 31;
    const int wm = (warp & 3) * 32;
    const int wn = (warp >> 2) * 32;
    const int bm0 = blockIdx.y * 128;

    float c[2][4][4];
#pragma unroll
    for (int mt = 0; mt < 2; mt++)
#pragma unroll
        for (int nt = 0; nt < 4; nt++)
#pragma unroll
            for (int r = 0; r < 4; r++) c[mt][nt][r] = 0.f;

    const float* Ablk = A + bm0 * lda;

    for (int k0 = 0; k0 < H_; k0 += BK) {
#pragma unroll
        for (int i = 0; i < 4; i++) {
            int cc = tid + i * 256;
            int r = cc >> 3, kc = (cc & 7) << 2;
            cp16(&As[r][kc], Ablk + r * lda + k0 + kc);
        }
#pragma unroll
        for (int i = 0; i < 2; i++) {
            int cc = tid + i * 256;
            int r = cc >> 3, kc = (cc & 7) << 2;
            cp16(&Bs[r][kc], Bw + r * H_ + k0 + kc);
        }
        asm volatile("cp.async.commit_group;\n" ::);
        asm volatile("cp.async.wait_group 0;\n" ::);
        __syncthreads();

#pragma unroll
        for (int kk = 0; kk < 4; kk++) {
            const int kb = kk * 8 + (lane & 3);
            uint32_t af[2][4], bf[4][2];
#pragma unroll
            for (int mt = 0; mt < 2; mt++) {
                int m = wm + mt * 16 + (lane >> 2);
                af[mt][0] = __float_as_uint(As[m    ][kb    ]);
                af[mt][1] = __float_as_uint(As[m + 8][kb    ]);
                af[mt][2] = __float_as_uint(As[m    ][kb + 4]);
                af[mt][3] = __float_as_uint(As[m + 8][kb + 4]);
            }
#pragma unroll
            for (int nt = 0; nt < 4; nt++) {
                int n = wn + nt * 8 + (lane >> 2);
                bf[nt][0] = __float_as_uint(Bs[n][kb    ]);
                bf[nt][1] = __float_as_uint(Bs[n][kb + 4]);
            }
#pragma unroll
            for (int mt = 0; mt < 2; mt++)
#pragma unroll
                for (int nt = 0; nt < 4; nt++)
                    asm volatile(
                        "mma.sync.aligned.m16n8k8.row.col.f32.tf32.tf32.f32 "
                        "{%0,%1,%2,%3}, {%4,%5,%6,%7}, {%8,%9}, {%0,%1,%2,%3};\n"
                        : "+f"(c[mt][nt][0]), "+f"(c[mt][nt][1]),
                          "+f"(c[mt][nt][2]), "+f"(c[mt][nt][3])
                        : "r"(af[mt][0]), "r"(af[mt][1]),
                          "r"(af[mt][2]), "r"(af[mt][3]),
                          "r"(bf[nt][0]), "r"(bf[nt][1]));
        }
        __syncthreads();
    }

#pragma unroll
    for (int mt = 0; mt < 2; mt++) {
#pragma unroll
        for (int nt = 0; nt < 4; nt++) {
            int m = bm0 + wm + mt * 16 + (lane >> 2);
            int n = wn + nt * 8 + ((lane & 3) << 1);
            float bv0 = bias[n], bv1 = bias[n + 1];
            float v0 = c[mt][nt][0] + bv0;
            float v1 = c[mt][nt][1] + bv1;
            float v2 = c[mt][nt][2] + bv0;
            float v3 = c[mt][nt][3] + bv1;
            out[m * (T_ * O_) + t * O_ + n]           = v0;
            out[m * (T_ * O_) + t * O_ + n + 1]       = v1;
            out[(m + 8) * (T_ * O_) + t * O_ + n]     = v2;
            out[(m + 8) * (T_ * O_) + t * O_ + n + 1] = v3;
            x0n[m * KC0 + n]           = to_tf32(v0);
            x0n[m * KC0 + n + 1]       = to_tf32(v1);
            x0n[(m + 8) * KC0 + n]     = to_tf32(v2);
            x0n[(m + 8) * KC0 + n + 1] = to_tf32(v3);
        }
    }
}

// ---------------------------------------------------------------------------
// Launch. ncu -s 5 -c 1 captures launch 5 = layer-1 GEMM (t=0):
// 0 prep_all, 1 zero2, 2 zero2, 3 Gs, 4 L0(t0), 5 L1(t0).
// ---------------------------------------------------------------------------
extern "C" void kernel_launch(void* const* d_in, const int* in_sizes, int n_in,
                              void* d_out, int out_size)
{
    (void)in_sizes; (void)n_in; (void)out_size;
    const float* sIn  = (const float*)d_in[0];
    const float* Wih0 = (const float*)d_in[1];
    const float* Whh0 = (const float*)d_in[2];
    const float* bih0 = (const float*)d_in[3];
    const float* bhh0 = (const float*)d_in[4];
    const float* Wih1 = (const float*)d_in[5];
    const float* Whh1 = (const float*)d_in[6];
    const float* bih1 = (const float*)d_in[7];
    const float* bhh1 = (const float*)d_in[8];
    const float* Wout = (const float*)d_in[9];
    const float* bout = (const float*)d_in[10];
    float* out = (float*)d_out;

    float *xs, *Ws, *W0, *W1, *Wo, *b0, *b1, *Gs, *x0A, *x0B, *x1A, *x1B, *c1, *c2;
    cudaGetSymbolAddress((void**)&xs,  g_xs);
    cudaGetSymbolAddress((void**)&Ws,  g_Ws);
    cudaGetSymbolAddress((void**)&W0,  g_W0);
    cudaGetSymbolAddress((void**)&W1,  g_W1);
    cudaGetSymbolAddress((void**)&Wo,  g_Wo);
    cudaGetSymbolAddress((void**)&b0,  g_b0);
    cudaGetSymbolAddress((void**)&b1,  g_b1);
    cudaGetSymbolAddress((void**)&Gs,  g_Gs);
    cudaGetSymbolAddress((void**)&x0A, g_x0A);
    cudaGetSymbolAddress((void**)&x0B, g_x0B);
    cudaGetSymbolAddress((void**)&x1A, g_x1A);
    cudaGetSymbolAddress((void**)&x1B, g_x1B);
    cudaGetSymbolAddress((void**)&c1,  g_c1);
    cudaGetSymbolAddress((void**)&c2,  g_c2);

    static bool attr_done = false;
    if (!attr_done) {
        cudaFuncSetAttribute(gemm_fused<0>,
            cudaFuncAttributeMaxDynamicSharedMemorySize, SMEM_BYTES);
        cudaFuncSetAttribute(gemm_fused<1>,
            cudaFuncAttributeMaxDynamicSharedMemorySize, SMEM_BYTES);
        attr_done = true;
    }

    // launch 0: pack everything
    prep_all<<<4096, 256>>>(sIn, Wih0, Whh0, bih0, bhh0, Wih1, Whh1, bih1, bhh1,
                            Wout, xs, Ws, W0, W1, Wo, b0, b1);
    // launches 1-2: zero recurrent state (replay reset)
    zero2<<<4096, 256>>>(x0A, B_ * KC0, c1, B_ * H_);
    zero2<<<4096, 256>>>(x1A, B_ * KC1, c2, B_ * H_);

    // launch 3: Gs = static @ Ws^T + b0
    dim3 grid(G4 / BN, B_ / BM);   // (64, 32)
    gemm_fused<0><<<grid, 256, SMEM_BYTES>>>(IN_, xs, IN_, Ws, IN_,
                                             Gs, nullptr, b0,
                                             nullptr, nullptr, 0, nullptr, 0);

    float* x0b[2] = {x0A, x0B};
    float* x1b[2] = {x1A, x1B};
    dim3 gridOut(1, B_ / 128);     // (1, 32)

    for (int t = 0; t < T_; t++) {
        float* x0c = x0b[t & 1];
        float* x0n = x0b[(t + 1) & 1];
        float* x1c = x1b[t & 1];
        float* x1n = x1b[(t + 1) & 1];

        // layer 0: gates = [y|h1]@W0^T + Gs ; cell -> c1, h1 into x0n & x1c
        gemm_fused<1><<<grid, 256, SMEM_BYTES>>>(KC0, x0c, KC0, W0, KC0,
                                                 nullptr, Gs, nullptr,
                                                 c1, x0n + O_, KC0, x1c, KC1);

        // layer 1: gates = [h1|h2]@W1^T + b1 ; cell -> c2, h2 into x1n second half
        gemm_fused<1><<<grid, 256, SMEM_BYTES>>>(KC1, x1c, KC1, W1, KC1,
                                                 nullptr, nullptr, b1,
                                                 c2, x1n + H_, KC1, nullptr, 0);

        // output: y = h2 @ Wout^T + bout ; fused scatter + feedback into x0n
        gemm_out<<<gridOut, 256>>>(x1n + H_, KC1, Wo, bout, out, x0n, t);
    }
}

// round 15
// speedup vs baseline: 1.9090x; 1.1661x over previous
#include <cuda_runtime.h>
#include <cstdint>

// Problem constants
#define B_   4096
#define IN_  128
#define H_   1024
#define O_   64
#define T_   25
#define G4   (4*H_)        // 4096 gate columns (interleaved: col = 4*h + gate)
#define KC0  (O_ + H_)     // 1088  layer-0 dynamic K  [y | h1]
#define KC1  (2*H_)        // 2048  layer-1 K          [h1 | h2]

// ---------------------------------------------------------------------------
// Scratch (device globals; no allocation allowed)
// ---------------------------------------------------------------------------
__device__ float g_xs[B_*IN_];
__device__ float g_Ws[G4*IN_];
__device__ float g_W0[G4*KC0];
__device__ float g_W1[G4*KC1];
__device__ float g_Wo[O_*H_];
__device__ float g_b0[G4];
__device__ float g_b1[G4];
__device__ float g_Gs[B_*G4];
__device__ float g_x0A[B_*KC0];
__device__ float g_x0B[B_*KC0];
__device__ float g_x1A[B_*KC1];
__device__ float g_x1B[B_*KC1];
__device__ float g_c1[B_*H_];
__device__ float g_c2[B_*H_];

// ---------------------------------------------------------------------------
// Helpers
// ---------------------------------------------------------------------------
__device__ __forceinline__ float to_tf32(float x) {
    float r; asm("cvt.rna.tf32.f32 %0, %1;" : "=f"(r) : "f"(x)); return r;
}
__device__ __forceinline__ float fast_exp2(float x) {
    float r; asm("ex2.approx.f32 %0, %1;" : "=f"(r) : "f"(x)); return r;
}
__device__ __forceinline__ float fast_rcp(float x) {
    float r; asm("rcp.approx.f32 %0, %1;" : "=f"(r) : "f"(x)); return r;
}
__device__ __forceinline__ float sigmoid_f(float x) {
    x = fminf(fmaxf(x, -30.f), 30.f);
    float e = fast_exp2(-x * 1.4426950408889634f);
    return fast_rcp(1.f + e);
}
__device__ __forceinline__ float tanh_f(float x) {
    x = fminf(fmaxf(x, -15.f), 15.f);
    float e = fast_exp2(2.f * x * 1.4426950408889634f);
    return 1.f - 2.f * fast_rcp(e + 1.f);
}
__device__ __forceinline__ void cp16(void* s, const void* g) {
    uint32_t sa = (uint32_t)__cvta_generic_to_shared(s);
    asm volatile("cp.async.cg.shared.global [%0], [%1], 16;\n" :: "r"(sa), "l"(g));
}

// ---------------------------------------------------------------------------
// Prep: ONE kernel packs everything (tf32 + gate interleave + folded biases).
// ---------------------------------------------------------------------------
#define PN0 (B_*IN_)
#define PN1 (G4*IN_)
#define PN2 (G4*KC0)
#define PN3 (G4*KC1)
#define PN4 (O_*H_)
#define PN5 G4
#define PN6 G4
#define PTOT (PN0+PN1+PN2+PN3+PN4+PN5+PN6)

__global__ void prep_all(const float* __restrict__ sIn,
                         const float* __restrict__ Wih0, const float* __restrict__ Whh0,
                         const float* __restrict__ bih0, const float* __restrict__ bhh0,
                         const float* __restrict__ Wih1, const float* __restrict__ Whh1,
                         const float* __restrict__ bih1, const float* __restrict__ bhh1,
                         const float* __restrict__ Wout,
                         float* __restrict__ xs, float* __restrict__ Ws,
                         float* __restrict__ W0, float* __restrict__ W1,
                         float* __restrict__ Wo, float* __restrict__ b0,
                         float* __restrict__ b1)
{
    for (long long i = blockIdx.x * (long long)blockDim.x + threadIdx.x; i < PTOT;
         i += (long long)gridDim.x * blockDim.x) {
        long long j = i;
        if (j < PN0) { xs[j] = to_tf32(sIn[j]); continue; }
        j -= PN0;
        if (j < PN1) {
            int r = (int)(j / IN_), k = (int)(j - (long long)r * IN_);
            int p = (r & 3) * H_ + (r >> 2);
            Ws[j] = to_tf32(Wih0[p * (IN_ + O_) + k]);
            continue;
        }
        j -= PN1;
        if (j < PN2) {
            int r = (int)(j / KC0), k = (int)(j - (long long)r * KC0);
            int p = (r & 3) * H_ + (r >> 2);
            float v = (k < O_) ? Wih0[p * (IN_ + O_) + IN_ + k]
                               : Whh0[p * H_ + (k - O_)];
            W0[j] = to_tf32(v);
            continue;
        }
        j -= PN2;
        if (j < PN3) {
            int r = (int)(j / KC1), k = (int)(j - (long long)r * KC1);
            int p = (r & 3) * H_ + (r >> 2);
            float v = (k < H_) ? Wih1[p * H_ + k] : Whh1[p * H_ + (k - H_)];
            W1[j] = to_tf32(v);
            continue;
        }
        j -= PN3;
        if (j < PN4) { Wo[j] = to_tf32(Wout[j]); continue; }
        j -= PN4;
        if (j < PN5) {
            int p = ((int)j & 3) * H_ + ((int)j >> 2);
            b0[j] = bih0[p] + bhh0[p];
            continue;
        }
        j -= PN5;
        {
            int p = ((int)j & 3) * H_ + ((int)j >> 2);
            b1[j] = bih1[p] + bhh1[p];
        }
    }
}

__global__ void zero2(float* __restrict__ p1, int n1, float* __restrict__ p2, int n2)
{
    for (int i = blockIdx.x * blockDim.x + threadIdx.x; i < n1 + n2;
         i += gridDim.x * blockDim.x) {
        if (i < n1) p1[i] = 0.f; else p2[i - n1] = 0.f;
    }
}

// ---------------------------------------------------------------------------
// TF32 GEMM: acc[M,N] = A[M,K] * W[N,K]^T
// BM=128, BN=128, BK=32, 2-stage cp.async, 8 warps (2 M x 4 N), warp 64x32,
// mma.sync.m16n8k8.tf32, scalar LDS fragments (conflict-free, PAD=36).
// __launch_bounds__(256,2): 128-reg cap -> 2 CTAs/SM (smem 72KB allows 3).
// MODE 0: C = acc + bias (direct store; runs once)
// MODE 1: fused LSTM cell via SMEM-STAGED COALESCED epilogue (R13-proven).
// ---------------------------------------------------------------------------
#define BM 128
#define BN 128
#define BK 32
#define PAD 36
#define STG_A (BM*PAD)
#define STG_B (BN*PAD)
#define SMEM_BYTES (2*(STG_A+STG_B)*4)
#define EPI_LD 132         // epilogue smem row stride; 128*132*4 = 67.6KB <= 72KB

template<int MODE>
__global__ void __launch_bounds__(256, 2)
gemm_fused(int K,
           const float* __restrict__ A, int lda,
           const float* __restrict__ Bw, int ldb,
           float* __restrict__ C,
           const float* __restrict__ Ci,
           const float* __restrict__ bias,
           float* __restrict__ cst,
           float* __restrict__ hd1, int ldh1,
           float* __restrict__ hd2, int ldh2)
{
    extern __shared__ float sm[];
    float* Asm = sm;                 // [2][BM][PAD]
    float* Bsm = sm + 2 * STG_A;     // [2][BN][PAD]

    const int tid  = threadIdx.x;
    const int warp = tid >> 5;
    const int lane = tid & 31;
    const int wm = (warp & 1) * 64;   // warp M offset (2 warps along M)
    const int wn = (warp >> 1) * 32;  // warp N offset (4 warps along N)
    const int bm0 = blockIdx.y * BM;
    const int bn0 = blockIdx.x * BN;

    const float* Ablk = A + bm0 * lda;
    const float* Bblk = Bw + bn0 * ldb;

    float c[4][4][4];                 // mt(4 x m16) x nt(4 x n8) x 4
#pragma unroll
    for (int mt = 0; mt < 4; mt++)
#pragma unroll
        for (int nt = 0; nt < 4; nt++)
#pragma unroll
            for (int r = 0; r < 4; r++) c[mt][nt][r] = 0.f;

    const int numTiles = K / BK;

    auto loadStage = [&](int st, int k0) {
        float* As = Asm + st * STG_A;
        float* Bs = Bsm + st * STG_B;
#pragma unroll
        for (int i = 0; i < 4; i++) {             // A: 1024 16B chunks
            int cc = tid + i * 256;
            int r = cc >> 3, kc = (cc & 7) << 2;
            cp16(&As[r * PAD + kc], Ablk + r * lda + k0 + kc);
        }
#pragma unroll
        for (int i = 0; i < 4; i++) {             // B: 1024 16B chunks
            int cc = tid + i * 256;
            int r = cc >> 3, kc = (cc & 7) << 2;
            cp16(&Bs[r * PAD + kc], Bblk + r * ldb + k0 + kc);
        }
    };

    loadStage(0, 0);
    asm volatile("cp.async.commit_group;\n" ::);

    for (int it = 0; it < numTiles; ++it) {
        if (it + 1 < numTiles) {
            loadStage((it + 1) & 1, (it + 1) * BK);
            asm volatile("cp.async.commit_group;\n" ::);
            asm volatile("cp.async.wait_group 1;\n" ::);
        } else {
            asm volatile("cp.async.wait_group 0;\n" ::);
        }
        __syncthreads();

        const float* As = Asm + (it & 1) * STG_A;
        const float* Bs = Bsm + (it & 1) * STG_B;

#pragma unroll
        for (int kk = 0; kk < 4; kk++) {
            const int kb = kk * 8 + (lane & 3);
            uint32_t af[4][4], bf[4][2];
#pragma unroll
            for (int mt = 0; mt < 4; mt++) {
                int m = wm + mt * 16 + (lane >> 2);
                af[mt][0] = __float_as_uint(As[m * PAD + kb]);
                af[mt][1] = __float_as_uint(As[(m + 8) * PAD + kb]);
                af[mt][2] = __float_as_uint(As[m * PAD + kb + 4]);
                af[mt][3] = __float_as_uint(As[(m + 8) * PAD + kb + 4]);
            }
#pragma unroll
            for (int nt = 0; nt < 4; nt++) {
                int n = wn + nt * 8 + (lane >> 2);
                bf[nt][0] = __float_as_uint(Bs[n * PAD + kb]);
                bf[nt][1] = __float_as_uint(Bs[n * PAD + kb + 4]);
            }
#pragma unroll
            for (int mt = 0; mt < 4; mt++)
#pragma unroll
                for (int nt = 0; nt < 4; nt++)
                    asm volatile(
                        "mma.sync.aligned.m16n8k8.row.col.f32.tf32.tf32.f32 "
                        "{%0,%1,%2,%3}, {%4,%5,%6,%7}, {%8,%9}, {%0,%1,%2,%3};\n"
                        : "+f"(c[mt][nt][0]), "+f"(c[mt][nt][1]),
                          "+f"(c[mt][nt][2]), "+f"(c[mt][nt][3])
                        : "r"(af[mt][0]), "r"(af[mt][1]),
                          "r"(af[mt][2]), "r"(af[mt][3]),
                          "r"(bf[nt][0]), "r"(bf[nt][1]));
        }
        __syncthreads();
    }

    if (MODE == 0) {
        // direct store (runs once per replay; coalescing non-critical)
#pragma unroll
        for (int mt = 0; mt < 4; mt++) {
#pragma unroll
            for (int nt = 0; nt < 4; nt++) {
                int m = bm0 + wm + mt * 16 + (lane >> 2);
                int n = bn0 + wn + nt * 8 + ((lane & 3) << 1);
                float bv0 = bias[n], bv1 = bias[n + 1];
                C[m * G4 + n]           = c[mt][nt][0] + bv0;
                C[m * G4 + n + 1]       = c[mt][nt][1] + bv1;
                C[(m + 8) * G4 + n]     = c[mt][nt][2] + bv0;
                C[(m + 8) * G4 + n + 1] = c[mt][nt][3] + bv1;
            }
        }
    } else {
        // ---- staged, coalesced fused-cell epilogue (R13 pattern, BN=128) ----
        float* Gsm = sm;   // mainloop buffers dead; 128*132 floats = 67.6KB
#pragma unroll
        for (int mt = 0; mt < 4; mt++) {
#pragma unroll
            for (int nt = 0; nt < 4; nt++) {
                int m = wm + mt * 16 + (lane >> 2);
                int n = wn + nt * 8 + ((lane & 3) << 1);
                Gsm[m * EPI_LD + n]           = c[mt][nt][0];
                Gsm[m * EPI_LD + n + 1]       = c[mt][nt][1];
                Gsm[(m + 8) * EPI_LD + n]     = c[mt][nt][2];
                Gsm[(m + 8) * EPI_LD + n + 1] = c[mt][nt][3];
            }
        }
        __syncthreads();

        const int hbase = bn0 >> 2;   // 32 h-values per CTA
#pragma unroll
        for (int i = 0; i < 16; i++) {
            int idx = tid + i * 256;          // 4096 cells = 128 rows x 32 h
            int h = idx & 31;
            int r = idx >> 5;
            int rg = bm0 + r;
            int hg = hbase + h;

            float4 g = *(float4*)&Gsm[r * EPI_LD + (h << 2)];
            if (Ci) {
                const float4 ci = *(const float4*)(Ci + (long long)rg * G4 + bn0 + (h << 2));
                g.x += ci.x; g.y += ci.y; g.z += ci.z; g.w += ci.w;
            } else {
                const float4 bb = *(const float4*)(bias + bn0 + (h << 2));
                g.x += bb.x; g.y += bb.y; g.z += bb.z; g.w += bb.w;
            }
            float cold = cst[rg * H_ + hg];
            float I = sigmoid_f(g.x), F = sigmoid_f(g.y);
            float G = tanh_f(g.z),    Oo = sigmoid_f(g.w);
            float nc = F * cold + I * G;
            float nh = to_tf32(Oo * tanh_f(nc));
            cst[rg * H_ + hg]   = nc;
            hd1[rg * ldh1 + hg] = nh;
            if (hd2) hd2[rg * ldh2 + hg] = nh;
        }
    }
}

// ---------------------------------------------------------------------------
// Output GEMM (N=64), unchanged from R13 (proven): y = h2 @ Wout^T + bout,
// fused scatter + tf32 feedback into x0_next[:, 0:64]. grid (1, 32).
// ---------------------------------------------------------------------------
__global__ void __launch_bounds__(256)
gemm_out(const float* __restrict__ A, int lda,
         const float* __restrict__ Bw,
         const float* __restrict__ bias,
         float* __restrict__ out, float* __restrict__ x0n, int t)
{
    __shared__ float As[128][BK + 4];
    __shared__ float Bs[64][BK + 4];

    const int tid  = threadIdx.x;
    const int warp = tid >> 5;
    const int lane = tid & 31;
    const int wm = (warp & 3) * 32;
    const int wn = (warp >> 2) * 32;
    const int bm0 = blockIdx.y * 128;

    float c[2][4][4];
#pragma unroll
    for (int mt = 0; mt < 2; mt++)
#pragma unroll
        for (int nt = 0; nt < 4; nt++)
#pragma unroll
            for (int r = 0; r < 4; r++) c[mt][nt][r] = 0.f;

    const float* Ablk = A + bm0 * lda;

    for (int k0 = 0; k0 < H_; k0 += BK) {
#pragma unroll
        for (int i = 0; i < 4; i++) {
            int cc = tid + i * 256;
            int r = cc >> 3, kc = (cc & 7) << 2;
            cp16(&As[r][kc], Ablk + r * lda + k0 + kc);
        }
#pragma unroll
        for (int i = 0; i < 2; i++) {
            int cc = tid + i * 256;
            int r = cc >> 3, kc = (cc & 7) << 2;
            cp16(&Bs[r][kc], Bw + r * H_ + k0 + kc);
        }
        asm volatile("cp.async.commit_group;\n" ::);
        asm volatile("cp.async.wait_group 0;\n" ::);
        __syncthreads();

#pragma unroll
        for (int kk = 0; kk < 4; kk++) {
            const int kb = kk * 8 + (lane & 3);
            uint32_t af[2][4], bf[4][2];
#pragma unroll
            for (int mt = 0; mt < 2; mt++) {
                int m = wm + mt * 16 + (lane >> 2);
                af[mt][0] = __float_as_uint(As[m    ][kb    ]);
                af[mt][1] = __float_as_uint(As[m + 8][kb    ]);
                af[mt][2] = __float_as_uint(As[m    ][kb + 4]);
                af[mt][3] = __float_as_uint(As[m + 8][kb + 4]);
            }
#pragma unroll
            for (int nt = 0; nt < 4; nt++) {
                int n = wn + nt * 8 + (lane >> 2);
                bf[nt][0] = __float_as_uint(Bs[n][kb    ]);
                bf[nt][1] = __float_as_uint(Bs[n][kb + 4]);
            }
#pragma unroll
            for (int mt = 0; mt < 2; mt++)
#pragma unroll
                for (int nt = 0; nt < 4; nt++)
                    asm volatile(
                        "mma.sync.aligned.m16n8k8.row.col.f32.tf32.tf32.f32 "
                        "{%0,%1,%2,%3}, {%4,%5,%6,%7}, {%8,%9}, {%0,%1,%2,%3};\n"
                        : "+f"(c[mt][nt][0]), "+f"(c[mt][nt][1]),
                          "+f"(c[mt][nt][2]), "+f"(c[mt][nt][3])
                        : "r"(af[mt][0]), "r"(af[mt][1]),
                          "r"(af[mt][2]), "r"(af[mt][3]),
                          "r"(bf[nt][0]), "r"(bf[nt][1]));
        }
        __syncthreads();
    }

#pragma unroll
    for (int mt = 0; mt < 2; mt++) {
#pragma unroll
        for (int nt = 0; nt < 4; nt++) {
            int m = bm0 + wm + mt * 16 + (lane >> 2);
            int n = wn + nt * 8 + ((lane & 3) << 1);
            float bv0 = bias[n], bv1 = bias[n + 1];
            float v0 = c[mt][nt][0] + bv0;
            float v1 = c[mt][nt][1] + bv1;
            float v2 = c[mt][nt][2] + bv0;
            float v3 = c[mt][nt][3] + bv1;
            out[m * (T_ * O_) + t * O_ + n]           = v0;
            out[m * (T_ * O_) + t * O_ + n + 1]       = v1;
            out[(m + 8) * (T_ * O_) + t * O_ + n]     = v2;
            out[(m + 8) * (T_ * O_) + t * O_ + n + 1] = v3;
            x0n[m * KC0 + n]           = to_tf32(v0);
            x0n[m * KC0 + n + 1]       = to_tf32(v1);
            x0n[(m + 8) * KC0 + n]     = to_tf32(v2);
            x0n[(m + 8) * KC0 + n + 1] = to_tf32(v3);
        }
    }
}

// ---------------------------------------------------------------------------
// Launch. ncu -s 5 -c 1 captures launch 5 = layer-1 GEMM (t=0):
// 0 prep_all, 1 zero2, 2 zero2, 3 Gs, 4 L0(t0), 5 L1(t0).
// ---------------------------------------------------------------------------
extern "C" void kernel_launch(void* const* d_in, const int* in_sizes, int n_in,
                              void* d_out, int out_size)
{
    (void)in_sizes; (void)n_in; (void)out_size;
    const float* sIn  = (const float*)d_in[0];
    const float* Wih0 = (const float*)d_in[1];
    const float* Whh0 = (const float*)d_in[2];
    const float* bih0 = (const float*)d_in[3];
    const float* bhh0 = (const float*)d_in[4];
    const float* Wih1 = (const float*)d_in[5];
    const float* Whh1 = (const float*)d_in[6];
    const float* bih1 = (const float*)d_in[7];
    const float* bhh1 = (const float*)d_in[8];
    const float* Wout = (const float*)d_in[9];
    const float* bout = (const float*)d_in[10];
    float* out = (float*)d_out;

    float *xs, *Ws, *W0, *W1, *Wo, *b0, *b1, *Gs, *x0A, *x0B, *x1A, *x1B, *c1, *c2;
    cudaGetSymbolAddress((void**)&xs,  g_xs);
    cudaGetSymbolAddress((void**)&Ws,  g_Ws);
    cudaGetSymbolAddress((void**)&W0,  g_W0);
    cudaGetSymbolAddress((void**)&W1,  g_W1);
    cudaGetSymbolAddress((void**)&Wo,  g_Wo);
    cudaGetSymbolAddress((void**)&b0,  g_b0);
    cudaGetSymbolAddress((void**)&b1,  g_b1);
    cudaGetSymbolAddress((void**)&Gs,  g_Gs);
    cudaGetSymbolAddress((void**)&x0A, g_x0A);
    cudaGetSymbolAddress((void**)&x0B, g_x0B);
    cudaGetSymbolAddress((void**)&x1A, g_x1A);
    cudaGetSymbolAddress((void**)&x1B, g_x1B);
    cudaGetSymbolAddress((void**)&c1,  g_c1);
    cudaGetSymbolAddress((void**)&c2,  g_c2);

    static bool attr_done = false;
    if (!attr_done) {
        cudaFuncSetAttribute(gemm_fused<0>,
            cudaFuncAttributeMaxDynamicSharedMemorySize, SMEM_BYTES);
        cudaFuncSetAttribute(gemm_fused<1>,
            cudaFuncAttributeMaxDynamicSharedMemorySize, SMEM_BYTES);
        attr_done = true;
    }

    // launch 0: pack everything
    prep_all<<<4096, 256>>>(sIn, Wih0, Whh0, bih0, bhh0, Wih1, Whh1, bih1, bhh1,
                            Wout, xs, Ws, W0, W1, Wo, b0, b1);
    // launches 1-2: zero recurrent state (replay reset)
    zero2<<<4096, 256>>>(x0A, B_ * KC0, c1, B_ * H_);
    zero2<<<4096, 256>>>(x1A, B_ * KC1, c2, B_ * H_);

    // launch 3: Gs = static @ Ws^T + b0
    dim3 grid(G4 / BN, B_ / BM);   // (32, 32)
    gemm_fused<0><<<grid, 256, SMEM_BYTES>>>(IN_, xs, IN_, Ws, IN_,
                                             Gs, nullptr, b0,
                                             nullptr, nullptr, 0, nullptr, 0);

    float* x0b[2] = {x0A, x0B};
    float* x1b[2] = {x1A, x1B};
    dim3 gridOut(1, B_ / 128);     // (1, 32)

    for (int t = 0; t < T_; t++) {
        float* x0c = x0b[t & 1];
        float* x0n = x0b[(t + 1) & 1];
        float* x1c = x1b[t & 1];
        float* x1n = x1b[(t + 1) & 1];

        // layer 0: gates = [y|h1]@W0^T + Gs ; cell -> c1, h1 into x0n & x1c
        gemm_fused<1><<<grid, 256, SMEM_BYTES>>>(KC0, x0c, KC0, W0, KC0,
                                                 nullptr, Gs, nullptr,
                                                 c1, x0n + O_, KC0, x1c, KC1);

        // layer 1: gates = [h1|h2]@W1^T + b1 ; cell -> c2, h2 into x1n 2nd half
        gemm_fused<1><<<grid, 256, SMEM_BYTES>>>(KC1, x1c, KC1, W1, KC1,
                                                 nullptr, nullptr, b1,
                                                 c2, x1n + H_, KC1, nullptr, 0);

        // output: y = h2 @ Wout^T + bout ; fused scatter + feedback into x0n
        gemm_out<<<gridOut, 256>>>(x1n + H_, KC1, Wo, bout, out, x0n, t);
    }
}

// round 17
// speedup vs baseline: 2.1006x; 1.1004x over previous
#include <cuda_runtime.h>
#include <cstdint>

// Problem constants
#define B_   4096
#define IN_  128
#define H_   1024
#define O_   64
#define T_   25
#define G4   (4*H_)        // 4096 gate columns (interleaved: col = 4*h + gate)
#define KC0  (O_ + H_)     // 1088  layer-0 dynamic K  [y | h1]
#define KC1  (2*H_)        // 2048  layer-1 K          [h1 | h2]

// ---------------------------------------------------------------------------
// Scratch (device globals; no allocation allowed)
// ---------------------------------------------------------------------------
__device__ float g_xs[B_*IN_];
__device__ float g_Ws[G4*IN_];
__device__ float g_W0[G4*KC0];
__device__ float g_W1[G4*KC1];
__device__ float g_Wo[O_*H_];
__device__ float g_b0[G4];
__device__ float g_b1[G4];
__device__ float g_Gs[B_*G4];
__device__ float g_x0A[B_*KC0];
__device__ float g_x0B[B_*KC0];
__device__ float g_x1A[B_*KC1];
__device__ float g_x1B[B_*KC1];
__device__ float g_c1[B_*H_];
__device__ float g_c2[B_*H_];

// ---------------------------------------------------------------------------
// Helpers
// ---------------------------------------------------------------------------
__device__ __forceinline__ float to_tf32(float x) {
    float r; asm("cvt.rna.tf32.f32 %0, %1;" : "=f"(r) : "f"(x)); return r;
}
__device__ __forceinline__ float fast_exp2(float x) {
    float r; asm("ex2.approx.f32 %0, %1;" : "=f"(r) : "f"(x)); return r;
}
__device__ __forceinline__ float fast_rcp(float x) {
    float r; asm("rcp.approx.f32 %0, %1;" : "=f"(r) : "f"(x)); return r;
}
__device__ __forceinline__ float sigmoid_f(float x) {
    x = fminf(fmaxf(x, -30.f), 30.f);
    float e = fast_exp2(-x * 1.4426950408889634f);
    return fast_rcp(1.f + e);
}
__device__ __forceinline__ float tanh_f(float x) {
    x = fminf(fmaxf(x, -15.f), 15.f);
    float e = fast_exp2(2.f * x * 1.4426950408889634f);
    return 1.f - 2.f * fast_rcp(e + 1.f);
}
__device__ __forceinline__ void cp16(void* s, const void* g) {
    uint32_t sa = (uint32_t)__cvta_generic_to_shared(s);
    asm volatile("cp.async.cg.shared.global [%0], [%1], 16;\n" :: "r"(sa), "l"(g));
}
__device__ __forceinline__ void ldsm4(uint32_t& r0, uint32_t& r1,
                                      uint32_t& r2, uint32_t& r3, uint32_t addr) {
    asm volatile("ldmatrix.sync.aligned.m8n8.x4.shared.b16 {%0,%1,%2,%3}, [%4];\n"
                 : "=r"(r0), "=r"(r1), "=r"(r2), "=r"(r3) : "r"(addr));
}

// ---------------------------------------------------------------------------
// Prep: ONE kernel packs everything (tf32 + gate interleave + folded biases).
// ---------------------------------------------------------------------------
#define PN0 (B_*IN_)
#define PN1 (G4*IN_)
#define PN2 (G4*KC0)
#define PN3 (G4*KC1)
#define PN4 (O_*H_)
#define PN5 G4
#define PN6 G4
#define PTOT (PN0+PN1+PN2+PN3+PN4+PN5+PN6)

__global__ void prep_all(const float* __restrict__ sIn,
                         const float* __restrict__ Wih0, const float* __restrict__ Whh0,
                         const float* __restrict__ bih0, const float* __restrict__ bhh0,
                         const float* __restrict__ Wih1, const float* __restrict__ Whh1,
                         const float* __restrict__ bih1, const float* __restrict__ bhh1,
                         const float* __restrict__ Wout,
                         float* __restrict__ xs, float* __restrict__ Ws,
                         float* __restrict__ W0, float* __restrict__ W1,
                         float* __restrict__ Wo, float* __restrict__ b0,
                         float* __restrict__ b1)
{
    for (long long i = blockIdx.x * (long long)blockDim.x + threadIdx.x; i < PTOT;
         i += (long long)gridDim.x * blockDim.x) {
        long long j = i;
        if (j < PN0) { xs[j] = to_tf32(sIn[j]); continue; }
        j -= PN0;
        if (j < PN1) {
            int r = (int)(j / IN_), k = (int)(j - (long long)r * IN_);
            int p = (r & 3) * H_ + (r >> 2);
            Ws[j] = to_tf32(Wih0[p * (IN_ + O_) + k]);
            continue;
        }
        j -= PN1;
        if (j < PN2) {
            int r = (int)(j / KC0), k = (int)(j - (long long)r * KC0);
            int p = (r & 3) * H_ + (r >> 2);
            float v = (k < O_) ? Wih0[p * (IN_ + O_) + IN_ + k]
                               : Whh0[p * H_ + (k - O_)];
            W0[j] = to_tf32(v);
            continue;
        }
        j -= PN2;
        if (j < PN3) {
            int r = (int)(j / KC1), k = (int)(j - (long long)r * KC1);
            int p = (r & 3) * H_ + (r >> 2);
            float v = (k < H_) ? Wih1[p * H_ + k] : Whh1[p * H_ + (k - H_)];
            W1[j] = to_tf32(v);
            continue;
        }
        j -= PN3;
        if (j < PN4) { Wo[j] = to_tf32(Wout[j]); continue; }
        j -= PN4;
        if (j < PN5) {
            int p = ((int)j & 3) * H_ + ((int)j >> 2);
            b0[j] = bih0[p] + bhh0[p];
            continue;
        }
        j -= PN5;
        {
            int p = ((int)j & 3) * H_ + ((int)j >> 2);
            b1[j] = bih1[p] + bhh1[p];
        }
    }
}

__global__ void zero2(float* __restrict__ p1, int n1, float* __restrict__ p2, int n2)
{
    for (int i = blockIdx.x * blockDim.x + threadIdx.x; i < n1 + n2;
         i += gridDim.x * blockDim.x) {
        if (i < n1) p1[i] = 0.f; else p2[i - n1] = 0.f;
    }
}

// ---------------------------------------------------------------------------
// TF32 GEMM: acc[M,N] = A[M,K] * W[N,K]^T
// BM=128, BN=128, BK=32, 3-stage cp.async (prefetch distance 2, ONE barrier
// per tile), 8 warps (2 M x 4 N), warp 64x32, mma.sync.m16n8k8.tf32,
// ldmatrix.b16 fragment loads (R11-proven encoding; PAD=36 conflict-free).
// __launch_bounds__(256,2): 128-reg cap; smem 110.6KB -> 2 CTAs/SM (221KB).
// MODE 0: C = acc + bias (direct store; runs once)
// MODE 1: fused LSTM cell via SMEM-STAGED COALESCED epilogue (R13-proven),
//         now with a barrier before staging (closes R13/R15 latent race).
// ---------------------------------------------------------------------------
#define BM 128
#define BN 128
#define BK 32
#define PAD 36
#define STG_A (BM*PAD)
#define STG_B (BN*PAD)
#define SMEM_BYTES (3*(STG_A+STG_B)*4)
#define EPI_LD 132         // epilogue smem row stride; 128*132*4 = 67.6KB

template<int MODE>
__global__ void __launch_bounds__(256, 2)
gemm_fused(int K,
           const float* __restrict__ A, int lda,
           const float* __restrict__ Bw, int ldb,
           float* __restrict__ C,
           const float* __restrict__ Ci,
           const float* __restrict__ bias,
           float* __restrict__ cst,
           float* __restrict__ hd1, int ldh1,
           float* __restrict__ hd2, int ldh2)
{
    extern __shared__ float sm[];
    float* Asm = sm;                 // [3][BM][PAD]
    float* Bsm = sm + 3 * STG_A;     // [3][BN][PAD]

    const int tid  = threadIdx.x;
    const int warp = tid >> 5;
    const int lane = tid & 31;
    const int wm = (warp & 1) * 64;   // warp M offset (2 warps along M)
    const int wn = (warp >> 1) * 32;  // warp N offset (4 warps along N)
    const int bm0 = blockIdx.y * BM;
    const int bn0 = blockIdx.x * BN;

    const float* Ablk = A + bm0 * lda;
    const float* Bblk = Bw + bn0 * ldb;

    // ldmatrix per-thread source offsets (bytes, within a stage)
    const uint32_t smA_u = (uint32_t)__cvta_generic_to_shared(Asm);
    const uint32_t smB_u = (uint32_t)__cvta_generic_to_shared(Bsm);
    const int arow = wm + ((lane >> 3) & 1) * 8 + (lane & 7);
    const uint32_t aoff = (uint32_t)((arow * PAD + (lane >> 4) * 4) * 4);
    const int brow = wn + (lane >> 4) * 8 + (lane & 7);
    const uint32_t boff = (uint32_t)((brow * PAD + ((lane >> 3) & 1) * 4) * 4);

    float c[4][4][4];                 // mt(4 x m16) x nt(4 x n8) x 4
#pragma unroll
    for (int mt = 0; mt < 4; mt++)
#pragma unroll
        for (int nt = 0; nt < 4; nt++)
#pragma unroll
            for (int r = 0; r < 4; r++) c[mt][nt][r] = 0.f;

    const int numTiles = K / BK;

    auto loadStage = [&](int st, int k0) {
        float* As = Asm + st * STG_A;
        float* Bs = Bsm + st * STG_B;
#pragma unroll
        for (int i = 0; i < 4; i++) {             // A: 1024 16B chunks
            int cc = tid + i * 256;
            int r = cc >> 3, kc = (cc & 7) << 2;
            cp16(&As[r * PAD + kc], Ablk + r * lda + k0 + kc);
        }
#pragma unroll
        for (int i = 0; i < 4; i++) {             // B: 1024 16B chunks
            int cc = tid + i * 256;
            int r = cc >> 3, kc = (cc & 7) << 2;
            cp16(&Bs[r * PAD + kc], Bblk + r * ldb + k0 + kc);
        }
    };

    // prologue: stages 0,1 in flight (numTiles >= 4 at all call sites)
    loadStage(0, 0);
    asm volatile("cp.async.commit_group;\n" ::);
    loadStage(1, BK);
    asm volatile("cp.async.commit_group;\n" ::);

    int st = 0;                       // stage of tile `it` (mod-3 tracked)
    for (int it = 0; it < numTiles; ++it) {
        if (it + 1 < numTiles)
            asm volatile("cp.async.wait_group 1;\n" ::);   // stage `it` ready
        else
            asm volatile("cp.async.wait_group 0;\n" ::);
        __syncthreads();              // also: all warps done computing it-1

        if (it + 2 < numTiles) {      // refill stage (it+2)%3 = (it-1)%3
            int fs = st + 2; if (fs >= 3) fs -= 3;
            loadStage(fs, (it + 2) * BK);
            asm volatile("cp.async.commit_group;\n" ::);
        }

        const uint32_t aS = smA_u + (uint32_t)(st * STG_A * 4) + aoff;
        const uint32_t bS = smB_u + (uint32_t)(st * STG_B * 4) + boff;

#pragma unroll
        for (int kk = 0; kk < 4; kk++) {
            uint32_t af[4][4], bf[4][2];
#pragma unroll
            for (int mt = 0; mt < 4; mt++)
                ldsm4(af[mt][0], af[mt][1], af[mt][2], af[mt][3],
                      aS + (uint32_t)(mt * 16 * PAD * 4) + (uint32_t)(kk * 32));
            ldsm4(bf[0][0], bf[0][1], bf[1][0], bf[1][1],
                  bS + (uint32_t)(kk * 32));
            ldsm4(bf[2][0], bf[2][1], bf[3][0], bf[3][1],
                  bS + (uint32_t)(16 * PAD * 4) + (uint32_t)(kk * 32));
#pragma unroll
            for (int mt = 0; mt < 4; mt++)
#pragma unroll
                for (int nt = 0; nt < 4; nt++)
                    asm volatile(
                        "mma.sync.aligned.m16n8k8.row.col.f32.tf32.tf32.f32 "
                        "{%0,%1,%2,%3}, {%4,%5,%6,%7}, {%8,%9}, {%0,%1,%2,%3};\n"
                        : "+f"(c[mt][nt][0]), "+f"(c[mt][nt][1]),
                          "+f"(c[mt][nt][2]), "+f"(c[mt][nt][3])
                        : "r"(af[mt][0]), "r"(af[mt][1]),
                          "r"(af[mt][2]), "r"(af[mt][3]),
                          "r"(bf[nt][0]), "r"(bf[nt][1]));
        }
        if (++st == 3) st = 0;
    }

    if (MODE == 0) {
        // direct store (runs once per replay; coalescing non-critical)
#pragma unroll
        for (int mt = 0; mt < 4; mt++) {
#pragma unroll
            for (int nt = 0; nt < 4; nt++) {
                int m = bm0 + wm + mt * 16 + (lane >> 2);
                int n = bn0 + wn + nt * 8 + ((lane & 3) << 1);
                float bv0 = bias[n], bv1 = bias[n + 1];
                C[m * G4 + n]           = c[mt][nt][0] + bv0;
                C[m * G4 + n + 1]       = c[mt][nt][1] + bv1;
                C[(m + 8) * G4 + n]     = c[mt][nt][2] + bv0;
                C[(m + 8) * G4 + n + 1] = c[mt][nt][3] + bv1;
            }
        }
    } else {
        // ---- staged, coalesced fused-cell epilogue ----
        __syncthreads();   // all warps done reading stage buffers (close race)
        float* Gsm = sm;   // 128*132 floats = 67.6KB <= 110.6KB
#pragma unroll
        for (int mt = 0; mt < 4; mt++) {
#pragma unroll
            for (int nt = 0; nt < 4; nt++) {
                int m = wm + mt * 16 + (lane >> 2);
                int n = wn + nt * 8 + ((lane & 3) << 1);
                Gsm[m * EPI_LD + n]           = c[mt][nt][0];
                Gsm[m * EPI_LD + n + 1]       = c[mt][nt][1];
                Gsm[(m + 8) * EPI_LD + n]     = c[mt][nt][2];
                Gsm[(m + 8) * EPI_LD + n + 1] = c[mt][nt][3];
            }
        }
        __syncthreads();

        const int hbase = bn0 >> 2;   // 32 h-values per CTA
#pragma unroll
        for (int i = 0; i < 16; i++) {
            int idx = tid + i * 256;          // 4096 cells = 128 rows x 32 h
            int h = idx & 31;
            int r = idx >> 5;
            int rg = bm0 + r;
            int hg = hbase + h;

            float4 g = *(float4*)&Gsm[r * EPI_LD + (h << 2)];
            if (Ci) {
                const float4 ci = *(const float4*)(Ci + (long long)rg * G4 + bn0 + (h << 2));
                g.x += ci.x; g.y += ci.y; g.z += ci.z; g.w += ci.w;
            } else {
                const float4 bb = *(const float4*)(bias + bn0 + (h << 2));
                g.x += bb.x; g.y += bb.y; g.z += bb.z; g.w += bb.w;
            }
            float cold = cst[rg * H_ + hg];
            float I = sigmoid_f(g.x), F = sigmoid_f(g.y);
            float G = tanh_f(g.z),    Oo = sigmoid_f(g.w);
            float nc = F * cold + I * G;
            float nh = to_tf32(Oo * tanh_f(nc));
            cst[rg * H_ + hg]   = nc;
            hd1[rg * ldh1 + hg] = nh;
            if (hd2) hd2[rg * ldh2 + hg] = nh;
        }
    }
}

// ---------------------------------------------------------------------------
// Output GEMM (N=64), unchanged from R13 (proven): y = h2 @ Wout^T + bout,
// fused scatter + tf32 feedback into x0_next[:, 0:64]. grid (1, 32).
// ---------------------------------------------------------------------------
__global__ void __launch_bounds__(256)
gemm_out(const float* __restrict__ A, int lda,
         const float* __restrict__ Bw,
         const float* __restrict__ bias,
         float* __restrict__ out, float* __restrict__ x0n, int t)
{
    __shared__ float As[128][BK + 4];
    __shared__ float Bs[64][BK + 4];

    const int tid  = threadIdx.x;
    const int warp = tid >> 5;
    const int lane = tid & 31;
    const int wm = (warp & 3) * 32;
    const int wn = (warp >> 2) * 32;
    const int bm0 = blockIdx.y * 128;

    float c[2][4][4];
#pragma unroll
    for (int mt = 0; mt < 2; mt++)
#pragma unroll
        for (int nt = 0; nt < 4; nt++)
#pragma unroll
            for (int r = 0; r < 4; r++) c[mt][nt][r] = 0.f;

    const float* Ablk = A + bm0 * lda;

    for (int k0 = 0; k0 < H_; k0 += BK) {
#pragma unroll
        for (int i = 0; i < 4; i++) {
            int cc = tid + i * 256;
            int r = cc >> 3, kc = (cc & 7) << 2;
            cp16(&As[r][kc], Ablk + r * lda + k0 + kc);
        }
#pragma unroll
        for (int i = 0; i < 2; i++) {
            int cc = tid + i * 256;
            int r = cc >> 3, kc = (cc & 7) << 2;
            cp16(&Bs[r][kc], Bw + r * H_ + k0 + kc);
        }
        asm volatile("cp.async.commit_group;\n" ::);
        asm volatile("cp.async.wait_group 0;\n" ::);
        __syncthreads();

#pragma unroll
        for (int kk = 0; kk < 4; kk++) {
            const int kb = kk * 8 + (lane & 3);
            uint32_t af[2][4], bf[4][2];
#pragma unroll
            for (int mt = 0; mt < 2; mt++) {
                int m = wm + mt * 16 + (lane >> 2);
                af[mt][0] = __float_as_uint(As[m    ][kb    ]);
                af[mt][1] = __float_as_uint(As[m + 8][kb    ]);
                af[mt][2] = __float_as_uint(As[m    ][kb + 4]);
                af[mt][3] = __float_as_uint(As[m + 8][kb + 4]);
            }
#pragma unroll
            for (int nt = 0; nt < 4; nt++) {
                int n = wn + nt * 8 + (lane >> 2);
                bf[nt][0] = __float_as_uint(Bs[n][kb    ]);
                bf[nt][1] = __float_as_uint(Bs[n][kb + 4]);
            }
#pragma unroll
            for (int mt = 0; mt < 2; mt++)
#pragma unroll
                for (int nt = 0; nt < 4; nt++)
                    asm volatile(
                        "mma.sync.aligned.m16n8k8.row.col.f32.tf32.tf32.f32 "
                        "{%0,%1,%2,%3}, {%4,%5,%6,%7}, {%8,%9}, {%0,%1,%2,%3};\n"
                        : "+f"(c[mt][nt][0]), "+f"(c[mt][nt][1]),
                          "+f"(c[mt][nt][2]), "+f"(c[mt][nt][3])
                        : "r"(af[mt][0]), "r"(af[mt][1]),
                          "r"(af[mt][2]), "r"(af[mt][3]),
                          "r"(bf[nt][0]), "r"(bf[nt][1]));
        }
        __syncthreads();
    }

#pragma unroll
    for (int mt = 0; mt < 2; mt++) {
#pragma unroll
        for (int nt = 0; nt < 4; nt++) {
            int m = bm0 + wm + mt * 16 + (lane >> 2);
            int n = wn + nt * 8 + ((lane & 3) << 1);
            float bv0 = bias[n], bv1 = bias[n + 1];
            float v0 = c[mt][nt][0] + bv0;
            float v1 = c[mt][nt][1] + bv1;
            float v2 = c[mt][nt][2] + bv0;
            float v3 = c[mt][nt][3] + bv1;
            out[m * (T_ * O_) + t * O_ + n]           = v0;
            out[m * (T_ * O_) + t * O_ + n + 1]       = v1;
            out[(m + 8) * (T_ * O_) + t * O_ + n]     = v2;
            out[(m + 8) * (T_ * O_) + t * O_ + n + 1] = v3;
            x0n[m * KC0 + n]           = to_tf32(v0);
            x0n[m * KC0 + n + 1]       = to_tf32(v1);
            x0n[(m + 8) * KC0 + n]     = to_tf32(v2);
            x0n[(m + 8) * KC0 + n + 1] = to_tf32(v3);
        }
    }
}

// ---------------------------------------------------------------------------
// Launch. ncu -s 5 -c 1 captures launch 5 = layer-1 GEMM (t=0):
// 0 prep_all, 1 zero2, 2 zero2, 3 Gs, 4 L0(t0), 5 L1(t0).
// ---------------------------------------------------------------------------
extern "C" void kernel_launch(void* const* d_in, const int* in_sizes, int n_in,
                              void* d_out, int out_size)
{
    (void)in_sizes; (void)n_in; (void)out_size;
    const float* sIn  = (const float*)d_in[0];
    const float* Wih0 = (const float*)d_in[1];
    const float* Whh0 = (const float*)d_in[2];
    const float* bih0 = (const float*)d_in[3];
    const float* bhh0 = (const float*)d_in[4];
    const float* Wih1 = (const float*)d_in[5];
    const float* Whh1 = (const float*)d_in[6];
    const float* bih1 = (const float*)d_in[7];
    const float* bhh1 = (const float*)d_in[8];
    const float* Wout = (const float*)d_in[9];
    const float* bout = (const float*)d_in[10];
    float* out = (float*)d_out;

    float *xs, *Ws, *W0, *W1, *Wo, *b0, *b1, *Gs, *x0A, *x0B, *x1A, *x1B, *c1, *c2;
    cudaGetSymbolAddress((void**)&xs,  g_xs);
    cudaGetSymbolAddress((void**)&Ws,  g_Ws);
    cudaGetSymbolAddress((void**)&W0,  g_W0);
    cudaGetSymbolAddress((void**)&W1,  g_W1);
    cudaGetSymbolAddress((void**)&Wo,  g_Wo);
    cudaGetSymbolAddress((void**)&b0,  g_b0);
    cudaGetSymbolAddress((void**)&b1,  g_b1);
    cudaGetSymbolAddress((void**)&Gs,  g_Gs);
    cudaGetSymbolAddress((void**)&x0A, g_x0A);
    cudaGetSymbolAddress((void**)&x0B, g_x0B);
    cudaGetSymbolAddress((void**)&x1A, g_x1A);
    cudaGetSymbolAddress((void**)&x1B, g_x1B);
    cudaGetSymbolAddress((void**)&c1,  g_c1);
    cudaGetSymbolAddress((void**)&c2,  g_c2);

    static bool attr_done = false;
    if (!attr_done) {
        cudaFuncSetAttribute(gemm_fused<0>,
            cudaFuncAttributeMaxDynamicSharedMemorySize, SMEM_BYTES);
        cudaFuncSetAttribute(gemm_fused<1>,
            cudaFuncAttributeMaxDynamicSharedMemorySize, SMEM_BYTES);
        attr_done = true;
    }

    // launch 0: pack everything
    prep_all<<<4096, 256>>>(sIn, Wih0, Whh0, bih0, bhh0, Wih1, Whh1, bih1, bhh1,
                            Wout, xs, Ws, W0, W1, Wo, b0, b1);
    // launches 1-2: zero recurrent state (replay reset)
    zero2<<<4096, 256>>>(x0A, B_ * KC0, c1, B_ * H_);
    zero2<<<4096, 256>>>(x1A, B_ * KC1, c2, B_ * H_);

    // launch 3: Gs = static @ Ws^T + b0
    dim3 grid(G4 / BN, B_ / BM);   // (32, 32)
    gemm_fused<0><<<grid, 256, SMEM_BYTES>>>(IN_, xs, IN_, Ws, IN_,
                                             Gs, nullptr, b0,
                                             nullptr, nullptr, 0, nullptr, 0);

    float* x0b[2] = {x0A, x0B};
    float* x1b[2] = {x1A, x1B};
    dim3 gridOut(1, B_ / 128);     // (1, 32)

    for (int t = 0; t < T_; t++) {
        float* x0c = x0b[t & 1];
        float* x0n = x0b[(t + 1) & 1];
        float* x1c = x1b[t & 1];
        float* x1n = x1b[(t + 1) & 1];

        // layer 0: gates = [y|h1]@W0^T + Gs ; cell -> c1, h1 into x0n & x1c
        gemm_fused<1><<<grid, 256, SMEM_BYTES>>>(KC0, x0c, KC0, W0, KC0,
                                                 nullptr, Gs, nullptr,
                                                 c1, x0n + O_, KC0, x1c, KC1);

        // layer 1: gates = [h1|h2]@W1^T + b1 ; cell -> c2, h2 into x1n 2nd half
        gemm_fused<1><<<grid, 256, SMEM_BYTES>>>(KC1, x1c, KC1, W1, KC1,
                                                 nullptr, nullptr, b1,
                                                 c2, x1n + H_, KC1, nullptr, 0);

        // output: y = h2 @ Wout^T + bout ; fused scatter + feedback into x0n
        gemm_out<<<gridOut, 256>>>(x1n + H_, KC1, Wo, bout, out, x0n, t);
    }
}